// round 2
// baseline (speedup 1.0000x reference)
#include <cuda_runtime.h>
#include <cuda_bf16.h>
#include <cstdint>

#define NCH   16
#define DIMK  128
#define NB    131072
#define TPG   68
// smem: bias(512B) + 4 tiles of 128 rows x 272B (A_hi, A_lo, B_hi, B_lo)
#define TSTRIDE 272
#define TILE_B  (128 * TSTRIDE)
#define S_BIAS  0
#define S_PERM  512
#define S_AHI   1024
#define S_ALO   (S_AHI + TILE_B)
#define S_BHI   (S_ALO + TILE_B)
#define S_BLO   (S_BHI + TILE_B)
#define GEMM_SMEM (S_BLO + TILE_B)

// ---- scratch (static device globals: no allocation APIs) ----
__device__ float g_h[(size_t)NB * DIMK];     // intermediate h [B,128]
__device__ int   g_perm_src[NB];
__device__ int   g_perm_tgt[NB];
__device__ int   g_count[32];                // [0:16) src, [16:32) tgt
__device__ int   g_offset[32];
__device__ int   g_cursor[32];

// ------------------------------ helpers ------------------------------
static __device__ __forceinline__ uint32_t smem_u32(const void* p) {
    uint32_t a;
    asm("{ .reg .u64 t; cvta.to.shared.u64 t, %1; cvt.u32.u64 %0, t; }" : "=r"(a) : "l"(p));
    return a;
}
// fp32 -> (hi,lo) bf16 split of a float4 (two bf16x2 words each)
static __device__ __forceinline__ void split4(float4 v, uint2& hi, uint2& lo) {
    __nv_bfloat162 h01 = __floats2bfloat162_rn(v.x, v.y);
    __nv_bfloat162 h23 = __floats2bfloat162_rn(v.z, v.w);
    float2 f01 = __bfloat1622float2(h01);
    float2 f23 = __bfloat1622float2(h23);
    __nv_bfloat162 l01 = __floats2bfloat162_rn(v.x - f01.x, v.y - f01.y);
    __nv_bfloat162 l23 = __floats2bfloat162_rn(v.z - f23.x, v.w - f23.y);
    hi.x = reinterpret_cast<uint32_t&>(h01); hi.y = reinterpret_cast<uint32_t&>(h23);
    lo.x = reinterpret_cast<uint32_t&>(l01); lo.y = reinterpret_cast<uint32_t&>(l23);
}
static __device__ __forceinline__ void ldsm_x4(uint32_t* r, uint32_t a) {
    asm volatile("ldmatrix.sync.aligned.m8n8.x4.shared.b16 {%0,%1,%2,%3}, [%4];"
        : "=r"(r[0]), "=r"(r[1]), "=r"(r[2]), "=r"(r[3]) : "r"(a));
}
static __device__ __forceinline__ void ldsm_x2(uint32_t* r, uint32_t a) {
    asm volatile("ldmatrix.sync.aligned.m8n8.x2.shared.b16 {%0,%1}, [%2];"
        : "=r"(r[0]), "=r"(r[1]) : "r"(a));
}
static __device__ __forceinline__ void mma_bf16(float* d, const uint32_t* a, const uint32_t* b) {
    asm volatile(
        "mma.sync.aligned.m16n8k16.row.col.f32.bf16.bf16.f32 "
        "{%0,%1,%2,%3}, {%4,%5,%6,%7}, {%8,%9}, {%0,%1,%2,%3};"
        : "+f"(d[0]), "+f"(d[1]), "+f"(d[2]), "+f"(d[3])
        : "r"(a[0]), "r"(a[1]), "r"(a[2]), "r"(a[3]), "r"(b[0]), "r"(b[1]));
}

// ------------------------------ sort kernels ------------------------------
__global__ void k_init() {
    int t = threadIdx.x;
    if (t < 32) g_count[t] = 0;
}
__global__ void k_hist(const int* __restrict__ src, const int* __restrict__ tgt) {
    __shared__ int h[32];
    int t = threadIdx.x;
    if (t < 32) h[t] = 0;
    __syncthreads();
    for (int i = blockIdx.x * blockDim.x + t; i < NB; i += gridDim.x * blockDim.x) {
        atomicAdd(&h[src[i] & 15], 1);
        atomicAdd(&h[16 + (tgt[i] & 15)], 1);
    }
    __syncthreads();
    if (t < 32) atomicAdd(&g_count[t], h[t]);
}
__global__ void k_scan() {
    int t = threadIdx.x;
    if (t < 2) {
        int b = t * 16, acc = 0;
        for (int i = 0; i < 16; i++) {
            g_offset[b + i] = acc;
            g_cursor[b + i] = acc;
            acc += g_count[b + i];
        }
    }
}
// CTA-aggregated scatter: smem histogram -> one global atomic per chart -> local ranks.
__global__ void k_scatter(const int* __restrict__ idx, int which) {
    __shared__ int h[16], base[16];
    int* perm = which ? g_perm_tgt : g_perm_src;
    int cbase = which * 16;
    int t = threadIdx.x;
    if (t < 16) h[t] = 0;
    __syncthreads();
    int lo = blockIdx.x * 512;
    int hi = lo + 512; if (hi > NB) hi = NB;
    for (int i = lo + t; i < hi; i += blockDim.x) atomicAdd(&h[idx[i] & 15], 1);
    __syncthreads();
    if (t < 16) { base[t] = atomicAdd(&g_cursor[cbase + t], h[t]); h[t] = 0; }
    __syncthreads();
    for (int i = lo + t; i < hi; i += blockDim.x) {
        int c = idx[i] & 15;
        int r = atomicAdd(&h[c], 1);
        perm[base[c] + r] = i;
    }
}

// ------------------------------ grouped GEMM ------------------------------
// Y[m,:] = X[m,:] @ W[g]^T + bias[g]   for rows m grouped by chart g.
// Warp layout: 8 warps = 4 (M strips of 32) x 2 (N halves of 64).
// Split-bf16: D = AhiBhi + AloBhi + AhiBlo, fp32 accumulation in registers.
__global__ void __launch_bounds__(256, 1)
gemm_group(const float* __restrict__ Xin, const float* __restrict__ W,
           const float* __restrict__ bias, float* __restrict__ Yout, int pass) {
    extern __shared__ char smem[];
    uint32_t sb = smem_u32(smem);
    int tid = threadIdx.x, wid = tid >> 5, lane = tid & 31;
    int warp_m = wid & 3, warp_n = wid >> 2;
    int g = blockIdx.x / TPG, t0 = blockIdx.x % TPG;

    const int*   cnts = g_count  + pass * 16;
    const int*   offs = g_offset + pass * 16;
    const int*   perm = pass ? g_perm_tgt : g_perm_src;
    const float* X    = pass ? g_h : Xin;
    float*       Y    = pass ? Yout : g_h;
    int cnt = cnts[g], off = offs[g];

    float* sbias = (float*)(smem + S_BIAS);
    int*   sperm = (int*)(smem + S_PERM);
    if (tid < 128) sbias[tid] = bias[g * DIMK + tid];

    // Load W[g] once (L2-resident across CTAs): split into B_hi / B_lo bf16 tiles.
    {
        const float4* Wg = (const float4*)(W + (size_t)g * DIMK * DIMK);
        #pragma unroll
        for (int it = 0; it < 16; it++) {
            int idx = it * 256 + tid;
            int r = idx >> 5, c4 = idx & 31;
            float4 v = __ldg(Wg + idx);
            uint2 hi, lo; split4(v, hi, lo);
            uint32_t o = (uint32_t)r * TSTRIDE + c4 * 8;
            *(uint2*)(smem + S_BHI + o) = hi;
            *(uint2*)(smem + S_BLO + o) = lo;
        }
    }

    for (int t = t0; t * 128 < cnt; t += TPG) {
        int base = off + t * 128;
        int rows = cnt - t * 128; if (rows > 128) rows = 128;

        __syncthreads();   // prior iter / init reads done before overwriting smem
        if (tid < 128) sperm[tid] = (tid < rows) ? perm[base + tid] : 0;
        __syncthreads();

        // Gather A tile: 128 rows x 128 fp32, coalesced (32 float4/row = one warp/row).
        #pragma unroll
        for (int it = 0; it < 16; it++) {
            int idx = it * 256 + tid;
            int r = idx >> 5, c4 = idx & 31;
            const float4* row = (const float4*)(X + (size_t)sperm[r] * DIMK);
            float4 v = __ldg(row + c4);
            uint2 hi, lo; split4(v, hi, lo);
            uint32_t o = (uint32_t)r * TSTRIDE + c4 * 8;
            *(uint2*)(smem + S_AHI + o) = hi;
            *(uint2*)(smem + S_ALO + o) = lo;
        }
        __syncthreads();

        // ---- MMA mainloop: 8 k-steps of 16 ----
        float acc[2][8][4];
        #pragma unroll
        for (int mt = 0; mt < 2; mt++)
            #pragma unroll
            for (int nt = 0; nt < 8; nt++)
                #pragma unroll
                for (int i = 0; i < 4; i++) acc[mt][nt][i] = 0.f;

        #pragma unroll
        for (int ks = 0; ks < 8; ks++) {
            int kb = ks * 16;
            uint32_t ah[2][4], al[2][4];
            #pragma unroll
            for (int mt = 0; mt < 2; mt++) {
                uint32_t row = warp_m * 32 + mt * 16 + (lane & 15);
                uint32_t o = row * TSTRIDE + kb * 2 + ((lane >> 4) << 4);
                ldsm_x4(ah[mt], sb + S_AHI + o);
                ldsm_x4(al[mt], sb + S_ALO + o);
            }
            #pragma unroll
            for (int nt = 0; nt < 8; nt++) {
                uint32_t n = warp_n * 64 + nt * 8 + (lane & 7);
                uint32_t o = n * TSTRIDE + kb * 2 + (((lane >> 3) & 1) << 4);
                uint32_t bh[2], bl[2];
                ldsm_x2(bh, sb + S_BHI + o);
                ldsm_x2(bl, sb + S_BLO + o);
                #pragma unroll
                for (int mt = 0; mt < 2; mt++) {
                    mma_bf16(acc[mt][nt], ah[mt], bh);
                    mma_bf16(acc[mt][nt], al[mt], bh);
                    mma_bf16(acc[mt][nt], ah[mt], bl);
                }
            }
        }

        // ---- Epilogue: add bias, scatter rows via perm ----
        int gid = lane >> 2, tig = lane & 3;
        #pragma unroll
        for (int mt = 0; mt < 2; mt++) {
            int m0 = warp_m * 32 + mt * 16 + gid;   // rows m0 and m0+8
            long gr0 = (m0 < rows)     ? (long)sperm[m0]     : -1;
            long gr1 = (m0 + 8 < rows) ? (long)sperm[m0 + 8] : -1;
            #pragma unroll
            for (int nt = 0; nt < 8; nt++) {
                int n = warp_n * 64 + nt * 8 + tig * 2;
                float b0 = sbias[n], b1 = sbias[n + 1];
                if (gr0 >= 0) {
                    float2 o = { acc[mt][nt][0] + b0, acc[mt][nt][1] + b1 };
                    *(float2*)(Y + gr0 * DIMK + n) = o;
                }
                if (gr1 >= 0) {
                    float2 o = { acc[mt][nt][2] + b0, acc[mt][nt][3] + b1 };
                    *(float2*)(Y + gr1 * DIMK + n) = o;
                }
            }
        }
    }
}

// ------------------------------ launch ------------------------------
extern "C" void kernel_launch(void* const* d_in, const int* in_sizes, int n_in,
                              void* d_out, int out_size) {
    const float* z    = (const float*)d_in[0];
    const int*   src  = (const int*)  d_in[1];
    const int*   tgt  = (const int*)  d_in[2];
    const float* enc  = (const float*)d_in[3];
    const float* dec  = (const float*)d_in[4];
    const float* cpar = (const float*)d_in[5];
    const float* dpar = (const float*)d_in[6];
    float* out = (float*)d_out;

    cudaFuncSetAttribute(gemm_group, cudaFuncAttributeMaxDynamicSharedMemorySize, GEMM_SMEM);

    k_init<<<1, 32>>>();
    k_hist<<<256, 256>>>(src, tgt);
    k_scan<<<1, 32>>>();
    k_scatter<<<NB / 512, 256>>>(src, 0);
    k_scatter<<<NB / 512, 256>>>(tgt, 1);
    gemm_group<<<NCH * TPG, 256, GEMM_SMEM>>>(z, enc, cpar, out, 0);   // h = z @ enc^T + c
    gemm_group<<<NCH * TPG, 256, GEMM_SMEM>>>(z, dec, dpar, out, 1);   // out = h @ dec^T + d
}

// round 3
// speedup vs baseline: 1.7177x; 1.7177x over previous
#include <cuda_runtime.h>
#include <cuda_bf16.h>
#include <cstdint>

#define NCH   16
#define NPAIR 256
#define DIMK  128
#define NB    131072
#define TPP   10                 // tiles (M=64) per pair in grid; strided loop covers overflow
#define TSTRIDE 272

// ---- main gemm smem layout ----
#define S_BIAS  0
#define S_PERM  512
#define S_AHI   1024
#define S_ALO   (S_AHI + 64 * TSTRIDE)
#define S_BHI   (S_ALO + 64 * TSTRIDE)
#define S_BLO   (S_BHI + 128 * TSTRIDE)
#define MAIN_SMEM (S_BLO + 128 * TSTRIDE)     // 105472 B -> 2 CTAs/SM

// ---- precompute smem layout ----
#define P_A     0
#define P_B     (128 * TSTRIDE)
#define PRE_SMEM (2 * 128 * TSTRIDE)          // 69632 B

// ---- scratch ----
__device__ __nv_bfloat16 g_Whi[(size_t)NPAIR * DIMK * DIMK];
__device__ __nv_bfloat16 g_Wlo[(size_t)NPAIR * DIMK * DIMK];
__device__ float g_bias[NPAIR * DIMK];
__device__ int   g_perm[NB];
__device__ int   g_count[NPAIR];
__device__ int   g_offset[NPAIR];
__device__ int   g_cursor[NPAIR];

// ------------------------------ helpers ------------------------------
static __device__ __forceinline__ uint32_t smem_u32(const void* p) {
    uint32_t a;
    asm("{ .reg .u64 t; cvta.to.shared.u64 t, %1; cvt.u32.u64 %0, t; }" : "=r"(a) : "l"(p));
    return a;
}
static __device__ __forceinline__ void split4(float4 v, uint2& hi, uint2& lo) {
    __nv_bfloat162 h01 = __floats2bfloat162_rn(v.x, v.y);
    __nv_bfloat162 h23 = __floats2bfloat162_rn(v.z, v.w);
    float2 f01 = __bfloat1622float2(h01);
    float2 f23 = __bfloat1622float2(h23);
    __nv_bfloat162 l01 = __floats2bfloat162_rn(v.x - f01.x, v.y - f01.y);
    __nv_bfloat162 l23 = __floats2bfloat162_rn(v.z - f23.x, v.w - f23.y);
    hi.x = reinterpret_cast<uint32_t&>(h01); hi.y = reinterpret_cast<uint32_t&>(h23);
    lo.x = reinterpret_cast<uint32_t&>(l01); lo.y = reinterpret_cast<uint32_t&>(l23);
}
static __device__ __forceinline__ void ldsm_x4(uint32_t* r, uint32_t a) {
    asm volatile("ldmatrix.sync.aligned.m8n8.x4.shared.b16 {%0,%1,%2,%3}, [%4];"
        : "=r"(r[0]), "=r"(r[1]), "=r"(r[2]), "=r"(r[3]) : "r"(a));
}
static __device__ __forceinline__ void mma_bf16(float* d, const uint32_t* a, const uint32_t* b) {
    asm volatile(
        "mma.sync.aligned.m16n8k16.row.col.f32.bf16.bf16.f32 "
        "{%0,%1,%2,%3}, {%4,%5,%6,%7}, {%8,%9}, {%0,%1,%2,%3};"
        : "+f"(d[0]), "+f"(d[1]), "+f"(d[2]), "+f"(d[3])
        : "r"(a[0]), "r"(a[1]), "r"(a[2]), "r"(a[3]), "r"(b[0]), "r"(b[1]));
}
static __device__ __forceinline__ void cpasync16(uint32_t dst, const void* src) {
    asm volatile("cp.async.ca.shared.global [%0], [%1], 16;" :: "r"(dst), "l"(src));
}

// ------------------------------ sort ------------------------------
__global__ void k_init() { g_count[threadIdx.x] = 0; }

__global__ void k_hist(const int* __restrict__ src, const int* __restrict__ tgt) {
    __shared__ int h[NPAIR];
    int t = threadIdx.x;
    h[t] = 0;
    __syncthreads();
    for (int i = blockIdx.x * blockDim.x + t; i < NB; i += gridDim.x * blockDim.x) {
        int p = ((src[i] & 15) << 4) | (tgt[i] & 15);
        atomicAdd(&h[p], 1);
    }
    __syncthreads();
    atomicAdd(&g_count[t], h[t]);
}

__global__ void k_scan() {
    __shared__ int s[NPAIR];
    int t = threadIdx.x;
    s[t] = g_count[t];
    __syncthreads();
    // Hillis-Steele inclusive scan
    for (int d = 1; d < NPAIR; d <<= 1) {
        int add = (t >= d) ? s[t - d] : 0;
        __syncthreads();
        s[t] += add;
        __syncthreads();
    }
    int excl = (t == 0) ? 0 : s[t - 1];
    g_offset[t] = excl;
    g_cursor[t] = excl;
}

__global__ void k_scatter(const int* __restrict__ src, const int* __restrict__ tgt) {
    __shared__ int h[NPAIR], base[NPAIR];
    int t = threadIdx.x;
    h[t] = 0;
    __syncthreads();
    int lo = blockIdx.x * 2048, hi = lo + 2048;
    for (int i = lo + t; i < hi; i += 256) {
        int p = ((src[i] & 15) << 4) | (tgt[i] & 15);
        atomicAdd(&h[p], 1);
    }
    __syncthreads();
    base[t] = atomicAdd(&g_cursor[t], h[t]);
    h[t] = 0;
    __syncthreads();
    for (int i = lo + t; i < hi; i += 256) {
        int p = ((src[i] & 15) << 4) | (tgt[i] & 15);
        int r = atomicAdd(&h[p], 1);
        g_perm[base[p] + r] = i;
    }
}

// ------------------------------ precompute pair weights ------------------------------
// Wc = dec[t] @ enc[s] = I + E_d + E_e + E_d@E_e  (E = W - I, |E| ~ 0.01)
// E_d@E_e (magnitude ~1e-3) computed with a single bf16 MMA chain; rest in fp32 exact.
// bias = dec[t] @ c[s] + d[t].
__global__ void __launch_bounds__(256, 1)
k_precomp(const float* __restrict__ enc, const float* __restrict__ dec,
          const float* __restrict__ cpar, const float* __restrict__ dpar) {
    extern __shared__ char smem[];
    uint32_t sb = smem_u32(smem);
    int tid = threadIdx.x, wid = tid >> 5, lane = tid & 31;
    int wm = wid & 3, wn = wid >> 2;
    int p = blockIdx.x, s = p >> 4, t = p & 15;

    const float* decT = dec + (size_t)t * DIMK * DIMK;
    const float* encS = enc + (size_t)s * DIMK * DIMK;

    // A = E_d = dec[t] - I, row-major [d][r], single bf16
    {
        const float4* d4 = (const float4*)decT;
        #pragma unroll
        for (int it = 0; it < 16; it++) {
            int idx = it * 256 + tid;
            int d = idx >> 5, r4 = idx & 31;
            float4 v = __ldg(d4 + idx);
            int rb = r4 * 4;
            if (d == rb + 0) v.x -= 1.f;
            if (d == rb + 1) v.y -= 1.f;
            if (d == rb + 2) v.z -= 1.f;
            if (d == rb + 3) v.w -= 1.f;
            __nv_bfloat162 b01 = __floats2bfloat162_rn(v.x, v.y);
            __nv_bfloat162 b23 = __floats2bfloat162_rn(v.z, v.w);
            uint2 u; u.x = reinterpret_cast<uint32_t&>(b01); u.y = reinterpret_cast<uint32_t&>(b23);
            *(uint2*)(smem + P_A + d * TSTRIDE + r4 * 8) = u;
        }
    }
    // B = E_e^T: B[n=d'][k=r] = enc[s][r][d'] - (r==d')
    {
        const float4* e4 = (const float4*)encS;
        #pragma unroll
        for (int it = 0; it < 16; it++) {
            int idx = it * 256 + tid;
            int r = idx >> 5, c4 = idx & 31;
            float4 v = __ldg(e4 + idx);
            int cb = c4 * 4;
            if (r == cb + 0) v.x -= 1.f;
            if (r == cb + 1) v.y -= 1.f;
            if (r == cb + 2) v.z -= 1.f;
            if (r == cb + 3) v.w -= 1.f;
            float vv[4] = {v.x, v.y, v.z, v.w};
            #pragma unroll
            for (int j = 0; j < 4; j++)
                *(__nv_bfloat16*)(smem + P_B + (cb + j) * TSTRIDE + r * 2) = __float2bfloat16(vv[j]);
        }
    }
    __syncthreads();

    float acc[2][8][4];
    #pragma unroll
    for (int mt = 0; mt < 2; mt++)
        #pragma unroll
        for (int nt = 0; nt < 8; nt++)
            #pragma unroll
            for (int i = 0; i < 4; i++) acc[mt][nt][i] = 0.f;

    #pragma unroll
    for (int ks = 0; ks < 8; ks++) {
        int kb = ks * 16;
        uint32_t a[2][4];
        #pragma unroll
        for (int mt = 0; mt < 2; mt++) {
            uint32_t row = wm * 32 + mt * 16 + (lane & 15);
            ldsm_x4(a[mt], sb + P_A + row * TSTRIDE + kb * 2 + ((lane >> 4) << 4));
        }
        #pragma unroll
        for (int j = 0; j < 4; j++) {
            uint32_t n = wn * 64 + j * 16 + (lane & 15);
            uint32_t q[4];
            ldsm_x4(q, sb + P_B + n * TSTRIDE + kb * 2 + ((lane >> 4) << 4));
            uint32_t b0[2] = {q[0], q[2]}, b1[2] = {q[1], q[3]};
            #pragma unroll
            for (int mt = 0; mt < 2; mt++) {
                mma_bf16(acc[mt][j * 2 + 0], a[mt], b0);
                mma_bf16(acc[mt][j * 2 + 1], a[mt], b1);
            }
        }
    }

    // Epilogue: Wc = acc + dec + enc - I ; split to bf16 hi/lo
    int gid = lane >> 2, tig = lane & 3;
    __nv_bfloat16* Whi = g_Whi + (size_t)p * DIMK * DIMK;
    __nv_bfloat16* Wlo = g_Wlo + (size_t)p * DIMK * DIMK;
    #pragma unroll
    for (int mt = 0; mt < 2; mt++) {
        #pragma unroll
        for (int nt = 0; nt < 8; nt++) {
            int n = wn * 64 + nt * 8 + tig * 2;
            #pragma unroll
            for (int half = 0; half < 2; half++) {
                int row = wm * 32 + mt * 16 + gid + half * 8;
                float2 dv = *(const float2*)(decT + row * DIMK + n);
                float2 ev = *(const float2*)(encS + row * DIMK + n);
                float w0 = acc[mt][nt][half * 2 + 0] + dv.x + ev.x - (row == n ? 1.f : 0.f);
                float w1 = acc[mt][nt][half * 2 + 1] + dv.y + ev.y - (row == n + 1 ? 1.f : 0.f);
                __nv_bfloat162 hi = __floats2bfloat162_rn(w0, w1);
                float2 hf = __bfloat1622float2(hi);
                __nv_bfloat162 lo = __floats2bfloat162_rn(w0 - hf.x, w1 - hf.y);
                *(__nv_bfloat162*)(Whi + row * DIMK + n) = hi;
                *(__nv_bfloat162*)(Wlo + row * DIMK + n) = lo;
            }
        }
    }

    // bias
    if (tid < DIMK) {
        const float4* drow = (const float4*)(decT + tid * DIMK);
        const float4* cv4  = (const float4*)(cpar + s * DIMK);
        float b = dpar[t * DIMK + tid];
        #pragma unroll
        for (int r4 = 0; r4 < 32; r4++) {
            float4 w = __ldg(drow + r4);
            float4 c = __ldg(cv4 + r4);
            b += w.x * c.x + w.y * c.y + w.z * c.z + w.w * c.w;
        }
        g_bias[p * DIMK + tid] = b;
    }
}

// ------------------------------ fused main GEMM ------------------------------
// out[row,:] = z[row,:] @ Wc[p]^T + bias[p]  for rows grouped by pair p.
// M=64 x N=128 tiles, 8 warps = 2(M) x 4(N). Split-bf16 3-MMA, fp32 accum.
__global__ void __launch_bounds__(256, 2)
k_main(const float* __restrict__ Z, float* __restrict__ Y) {
    extern __shared__ char smem[];
    uint32_t sb = smem_u32(smem);
    int tid = threadIdx.x, wid = tid >> 5, lane = tid & 31;
    int wm = wid & 1, wn = wid >> 1;
    int p = blockIdx.x / TPP, t0 = blockIdx.x % TPP;

    int cnt = g_count[p], off = g_offset[p];
    if (t0 * 64 >= cnt) return;

    float* sbias = (float*)(smem + S_BIAS);
    int*   sperm = (int*)(smem + S_PERM);
    if (tid < 128) sbias[tid] = g_bias[p * DIMK + tid];

    // async-load pre-split W (B operand): rows n, 256B each, into TSTRIDE layout
    {
        const __nv_bfloat16* Whi = g_Whi + (size_t)p * DIMK * DIMK;
        const __nv_bfloat16* Wlo = g_Wlo + (size_t)p * DIMK * DIMK;
        #pragma unroll
        for (int it = 0; it < 8; it++) {
            int id = it * 256 + tid;        // 2048 chunks of 16B
            int row = id >> 4, c = id & 15;
            cpasync16(sb + S_BHI + row * TSTRIDE + c * 16, Whi + row * DIMK + c * 8);
            cpasync16(sb + S_BLO + row * TSTRIDE + c * 16, Wlo + row * DIMK + c * 8);
        }
        asm volatile("cp.async.commit_group;");
    }

    for (int t = t0; t * 64 < cnt; t += TPP) {
        int base = off + t * 64;
        int rows = cnt - t * 64; if (rows > 64) rows = 64;

        __syncthreads();   // prior iter epilogue done before smem overwrite
        if (tid < 64) sperm[tid] = g_perm[base + (tid < rows ? tid : 0)];
        __syncthreads();

        // gather A: 64 rows x 128 fp32, split to bf16 hi/lo
        #pragma unroll
        for (int it = 0; it < 8; it++) {
            int idx = it * 256 + tid;
            int r = idx >> 5, c4 = idx & 31;
            const float4* rowp = (const float4*)(Z + (size_t)sperm[r] * DIMK);
            float4 v = __ldg(rowp + c4);
            uint2 hi, lo; split4(v, hi, lo);
            *(uint2*)(smem + S_AHI + r * TSTRIDE + c4 * 8) = hi;
            *(uint2*)(smem + S_ALO + r * TSTRIDE + c4 * 8) = lo;
        }
        asm volatile("cp.async.wait_group 0;" ::: "memory");
        __syncthreads();

        float acc[2][4][4];
        #pragma unroll
        for (int mt = 0; mt < 2; mt++)
            #pragma unroll
            for (int nt = 0; nt < 4; nt++)
                #pragma unroll
                for (int i = 0; i < 4; i++) acc[mt][nt][i] = 0.f;

        #pragma unroll
        for (int ks = 0; ks < 8; ks++) {
            int kb = ks * 16;
            uint32_t ah[2][4], al[2][4];
            #pragma unroll
            for (int mt = 0; mt < 2; mt++) {
                uint32_t row = wm * 32 + mt * 16 + (lane & 15);
                uint32_t o = row * TSTRIDE + kb * 2 + ((lane >> 4) << 4);
                ldsm_x4(ah[mt], sb + S_AHI + o);
                ldsm_x4(al[mt], sb + S_ALO + o);
            }
            #pragma unroll
            for (int j = 0; j < 2; j++) {
                uint32_t n = wn * 32 + j * 16 + (lane & 15);
                uint32_t o = n * TSTRIDE + kb * 2 + ((lane >> 4) << 4);
                uint32_t qh[4], ql[4];
                ldsm_x4(qh, sb + S_BHI + o);
                ldsm_x4(ql, sb + S_BLO + o);
                uint32_t bh0[2] = {qh[0], qh[2]}, bh1[2] = {qh[1], qh[3]};
                uint32_t bl0[2] = {ql[0], ql[2]}, bl1[2] = {ql[1], ql[3]};
                #pragma unroll
                for (int mt = 0; mt < 2; mt++) {
                    mma_bf16(acc[mt][j * 2 + 0], ah[mt], bh0);
                    mma_bf16(acc[mt][j * 2 + 0], al[mt], bh0);
                    mma_bf16(acc[mt][j * 2 + 0], ah[mt], bl0);
                    mma_bf16(acc[mt][j * 2 + 1], ah[mt], bh1);
                    mma_bf16(acc[mt][j * 2 + 1], al[mt], bh1);
                    mma_bf16(acc[mt][j * 2 + 1], ah[mt], bl1);
                }
            }
        }

        // epilogue: bias + scatter
        int gid = lane >> 2, tig = lane & 3;
        #pragma unroll
        for (int mt = 0; mt < 2; mt++) {
            int m0 = wm * 32 + mt * 16 + gid;
            long gr0 = (m0 < rows)     ? (long)sperm[m0]     : -1;
            long gr1 = (m0 + 8 < rows) ? (long)sperm[m0 + 8] : -1;
            #pragma unroll
            for (int nt = 0; nt < 4; nt++) {
                int n = wn * 32 + nt * 8 + tig * 2;
                float b0 = sbias[n], b1 = sbias[n + 1];
                if (gr0 >= 0) {
                    float2 o = { acc[mt][nt][0] + b0, acc[mt][nt][1] + b1 };
                    *(float2*)(Y + gr0 * DIMK + n) = o;
                }
                if (gr1 >= 0) {
                    float2 o = { acc[mt][nt][2] + b0, acc[mt][nt][3] + b1 };
                    *(float2*)(Y + gr1 * DIMK + n) = o;
                }
            }
        }
    }
}

// ------------------------------ launch ------------------------------
extern "C" void kernel_launch(void* const* d_in, const int* in_sizes, int n_in,
                              void* d_out, int out_size) {
    const float* z    = (const float*)d_in[0];
    const int*   src  = (const int*)  d_in[1];
    const int*   tgt  = (const int*)  d_in[2];
    const float* enc  = (const float*)d_in[3];
    const float* dec  = (const float*)d_in[4];
    const float* cpar = (const float*)d_in[5];
    const float* dpar = (const float*)d_in[6];
    float* out = (float*)d_out;

    cudaFuncSetAttribute(k_precomp, cudaFuncAttributeMaxDynamicSharedMemorySize, PRE_SMEM);
    cudaFuncSetAttribute(k_main,    cudaFuncAttributeMaxDynamicSharedMemorySize, MAIN_SMEM);

    k_init<<<1, 256>>>();
    k_hist<<<256, 256>>>(src, tgt);
    k_scan<<<1, 256>>>();
    k_scatter<<<NB / 2048, 256>>>(src, tgt);
    k_precomp<<<NPAIR, 256, PRE_SMEM>>>(enc, dec, cpar, dpar);
    k_main<<<NPAIR * TPP, 256, MAIN_SMEM>>>(z, out);
}

// round 4
// speedup vs baseline: 2.1336x; 1.2421x over previous
#include <cuda_runtime.h>
#include <cuda_bf16.h>
#include <cstdint>

#define NCH   16
#define NPAIR 256
#define DIMK  128
#define NB    131072
#define TPP   2
#define TSTRIDE 272

// ---- main gemm smem layout ----
#define S_BIAS   0
#define S_PERM   512
#define S_STAGE  1024                         // 64 x 512B fp32 stage
#define S_AHI    (S_STAGE + 64 * 512)         // 33792
#define S_ALO    (S_AHI + 64 * TSTRIDE)
#define S_B      (S_ALO + 64 * TSTRIDE)
#define MAIN_SMEM (S_B + 128 * TSTRIDE)       // ~103.4 KB -> 2 CTAs/SM

// ---- precompute smem layout ----
#define P_A     0
#define P_B     (128 * TSTRIDE)
#define PRE_SMEM (2 * 128 * TSTRIDE)          // 69632 B

// ---- scratch ----
__device__ __align__(16) __nv_bfloat16 g_E[(size_t)NPAIR * DIMK * DIMK];  // Wc - I, bf16
__device__ float g_bias[NPAIR * DIMK];
__device__ int   g_perm[NB];
__device__ int   g_count[NPAIR];
__device__ int   g_offset[NPAIR];
__device__ int   g_cursor[NPAIR];

// ------------------------------ helpers ------------------------------
static __device__ __forceinline__ uint32_t smem_u32(const void* p) {
    uint32_t a;
    asm("{ .reg .u64 t; cvta.to.shared.u64 t, %1; cvt.u32.u64 %0, t; }" : "=r"(a) : "l"(p));
    return a;
}
static __device__ __forceinline__ void split4(float4 v, uint2& hi, uint2& lo) {
    __nv_bfloat162 h01 = __floats2bfloat162_rn(v.x, v.y);
    __nv_bfloat162 h23 = __floats2bfloat162_rn(v.z, v.w);
    float2 f01 = __bfloat1622float2(h01);
    float2 f23 = __bfloat1622float2(h23);
    __nv_bfloat162 l01 = __floats2bfloat162_rn(v.x - f01.x, v.y - f01.y);
    __nv_bfloat162 l23 = __floats2bfloat162_rn(v.z - f23.x, v.w - f23.y);
    hi.x = reinterpret_cast<uint32_t&>(h01); hi.y = reinterpret_cast<uint32_t&>(h23);
    lo.x = reinterpret_cast<uint32_t&>(l01); lo.y = reinterpret_cast<uint32_t&>(l23);
}
static __device__ __forceinline__ void ldsm_x4(uint32_t* r, uint32_t a) {
    asm volatile("ldmatrix.sync.aligned.m8n8.x4.shared.b16 {%0,%1,%2,%3}, [%4];"
        : "=r"(r[0]), "=r"(r[1]), "=r"(r[2]), "=r"(r[3]) : "r"(a));
}
static __device__ __forceinline__ void mma_bf16(float* d, const uint32_t* a, const uint32_t* b) {
    asm volatile(
        "mma.sync.aligned.m16n8k16.row.col.f32.bf16.bf16.f32 "
        "{%0,%1,%2,%3}, {%4,%5,%6,%7}, {%8,%9}, {%0,%1,%2,%3};"
        : "+f"(d[0]), "+f"(d[1]), "+f"(d[2]), "+f"(d[3])
        : "r"(a[0]), "r"(a[1]), "r"(a[2]), "r"(a[3]), "r"(b[0]), "r"(b[1]));
}
static __device__ __forceinline__ void cpasync16(uint32_t dst, const void* src) {
    asm volatile("cp.async.ca.shared.global [%0], [%1], 16;" :: "r"(dst), "l"(src));
}

// ------------------------------ sort ------------------------------
__global__ void k_init() { g_count[threadIdx.x] = 0; }

__global__ void k_hist(const int* __restrict__ src, const int* __restrict__ tgt) {
    __shared__ int h[NPAIR];
    int t = threadIdx.x;
    h[t] = 0;
    __syncthreads();
    for (int i = blockIdx.x * blockDim.x + t; i < NB; i += gridDim.x * blockDim.x) {
        int p = ((src[i] & 15) << 4) | (tgt[i] & 15);
        atomicAdd(&h[p], 1);
    }
    __syncthreads();
    atomicAdd(&g_count[t], h[t]);
}

__global__ void k_scan() {
    __shared__ int s[NPAIR];
    int t = threadIdx.x;
    s[t] = g_count[t];
    __syncthreads();
    for (int d = 1; d < NPAIR; d <<= 1) {
        int add = (t >= d) ? s[t - d] : 0;
        __syncthreads();
        s[t] += add;
        __syncthreads();
    }
    int excl = (t == 0) ? 0 : s[t - 1];
    g_offset[t] = excl;
    g_cursor[t] = excl;
}

__global__ void k_scatter(const int* __restrict__ src, const int* __restrict__ tgt) {
    __shared__ int h[NPAIR], base[NPAIR];
    int t = threadIdx.x;
    h[t] = 0;
    __syncthreads();
    int lo = blockIdx.x * 2048, hi = lo + 2048;
    for (int i = lo + t; i < hi; i += 256) {
        int p = ((src[i] & 15) << 4) | (tgt[i] & 15);
        atomicAdd(&h[p], 1);
    }
    __syncthreads();
    base[t] = atomicAdd(&g_cursor[t], h[t]);
    h[t] = 0;
    __syncthreads();
    for (int i = lo + t; i < hi; i += 256) {
        int p = ((src[i] & 15) << 4) | (tgt[i] & 15);
        int r = atomicAdd(&h[p], 1);
        g_perm[base[p] + r] = i;
    }
}

// ------------------------------ precompute pair weights ------------------------------
// E = Wc - I = E_d + E_e + E_d@E_e, Wc = dec[t]@enc[s].  E_d@E_e via one bf16 MMA chain.
// bias = dec[t] @ c[s] + d[t].
__global__ void __launch_bounds__(256, 1)
k_precomp(const float* __restrict__ enc, const float* __restrict__ dec,
          const float* __restrict__ cpar, const float* __restrict__ dpar) {
    extern __shared__ char smem[];
    uint32_t sb = smem_u32(smem);
    int tid = threadIdx.x, wid = tid >> 5, lane = tid & 31;
    int wm = wid & 3, wn = wid >> 2;
    int p = blockIdx.x, s = p >> 4, t = p & 15;

    const float* decT = dec + (size_t)t * DIMK * DIMK;
    const float* encS = enc + (size_t)s * DIMK * DIMK;

    // A = E_d = dec[t] - I
    {
        const float4* d4 = (const float4*)decT;
        #pragma unroll
        for (int it = 0; it < 16; it++) {
            int idx = it * 256 + tid;
            int d = idx >> 5, r4 = idx & 31;
            float4 v = __ldg(d4 + idx);
            int rb = r4 * 4;
            if (d == rb + 0) v.x -= 1.f;
            if (d == rb + 1) v.y -= 1.f;
            if (d == rb + 2) v.z -= 1.f;
            if (d == rb + 3) v.w -= 1.f;
            __nv_bfloat162 b01 = __floats2bfloat162_rn(v.x, v.y);
            __nv_bfloat162 b23 = __floats2bfloat162_rn(v.z, v.w);
            uint2 u; u.x = reinterpret_cast<uint32_t&>(b01); u.y = reinterpret_cast<uint32_t&>(b23);
            *(uint2*)(smem + P_A + d * TSTRIDE + r4 * 8) = u;
        }
    }
    // B = E_e^T: B[n][k] = enc[s][k][n] - (k==n)
    {
        const float4* e4 = (const float4*)encS;
        #pragma unroll
        for (int it = 0; it < 16; it++) {
            int idx = it * 256 + tid;
            int r = idx >> 5, c4 = idx & 31;
            float4 v = __ldg(e4 + idx);
            int cb = c4 * 4;
            if (r == cb + 0) v.x -= 1.f;
            if (r == cb + 1) v.y -= 1.f;
            if (r == cb + 2) v.z -= 1.f;
            if (r == cb + 3) v.w -= 1.f;
            float vv[4] = {v.x, v.y, v.z, v.w};
            #pragma unroll
            for (int j = 0; j < 4; j++)
                *(__nv_bfloat16*)(smem + P_B + (cb + j) * TSTRIDE + r * 2) = __float2bfloat16(vv[j]);
        }
    }
    __syncthreads();

    float acc[2][8][4];
    #pragma unroll
    for (int mt = 0; mt < 2; mt++)
        #pragma unroll
        for (int nt = 0; nt < 8; nt++)
            #pragma unroll
            for (int i = 0; i < 4; i++) acc[mt][nt][i] = 0.f;

    #pragma unroll
    for (int ks = 0; ks < 8; ks++) {
        int kb = ks * 16;
        uint32_t a[2][4];
        #pragma unroll
        for (int mt = 0; mt < 2; mt++) {
            uint32_t row = wm * 32 + mt * 16 + (lane & 15);
            ldsm_x4(a[mt], sb + P_A + row * TSTRIDE + kb * 2 + ((lane >> 4) << 4));
        }
        #pragma unroll
        for (int j = 0; j < 4; j++) {
            uint32_t n = wn * 64 + j * 16 + (lane & 15);
            uint32_t q[4];
            ldsm_x4(q, sb + P_B + n * TSTRIDE + kb * 2 + ((lane >> 4) << 4));
            uint32_t b0[2] = {q[0], q[2]}, b1[2] = {q[1], q[3]};
            #pragma unroll
            for (int mt = 0; mt < 2; mt++) {
                mma_bf16(acc[mt][j * 2 + 0], a[mt], b0);
                mma_bf16(acc[mt][j * 2 + 1], a[mt], b1);
            }
        }
    }

    // E = acc + dec + enc - 2I  (single bf16 store)
    int gid = lane >> 2, tig = lane & 3;
    __nv_bfloat16* Ep = g_E + (size_t)p * DIMK * DIMK;
    #pragma unroll
    for (int mt = 0; mt < 2; mt++) {
        #pragma unroll
        for (int nt = 0; nt < 8; nt++) {
            int n = wn * 64 + nt * 8 + tig * 2;
            #pragma unroll
            for (int half = 0; half < 2; half++) {
                int row = wm * 32 + mt * 16 + gid + half * 8;
                float2 dv = *(const float2*)(decT + row * DIMK + n);
                float2 ev = *(const float2*)(encS + row * DIMK + n);
                float w0 = acc[mt][nt][half * 2 + 0] + dv.x + ev.x - (row == n     ? 2.f : 0.f);
                float w1 = acc[mt][nt][half * 2 + 1] + dv.y + ev.y - (row == n + 1 ? 2.f : 0.f);
                *(__nv_bfloat162*)(Ep + row * DIMK + n) = __floats2bfloat162_rn(w0, w1);
            }
        }
    }

    // bias
    if (tid < DIMK) {
        const float4* drow = (const float4*)(decT + tid * DIMK);
        const float4* cv4  = (const float4*)(cpar + s * DIMK);
        float b = dpar[t * DIMK + tid];
        #pragma unroll
        for (int r4 = 0; r4 < 32; r4++) {
            float4 w = __ldg(drow + r4);
            float4 c = __ldg(cv4 + r4);
            b += w.x * c.x + w.y * c.y + w.z * c.z + w.w * c.w;
        }
        g_bias[p * DIMK + tid] = b;
    }
}

// ------------------------------ fused main GEMM ------------------------------
// out[row,:] = z[row,:] + z[row,:] @ E[p]^T + bias[p].
// M=64 tiles, 8 warps = 2(M) x 4(N). 2-chain split-bf16 (z_hi@E + z_lo@E), fp32 accum.
// cp.async stage pipeline: prefetch tile t+TPP raw fp32 while MMA(t) runs.
__global__ void __launch_bounds__(256, 2)
k_main(const float* __restrict__ Z, float* __restrict__ Y) {
    extern __shared__ char smem[];
    uint32_t sb = smem_u32(smem);
    int tid = threadIdx.x, wid = tid >> 5, lane = tid & 31;
    int wm = wid & 1, wn = wid >> 1;
    int p = blockIdx.x / TPP, t0 = blockIdx.x % TPP;

    int cnt = g_count[p], off = g_offset[p];
    if (t0 * 64 >= cnt) return;

    float* sbias = (float*)(smem + S_BIAS);
    int*   sperm = (int*)(smem + S_PERM);
    if (tid < 128) sbias[tid] = g_bias[p * DIMK + tid];

    // B (E tile) via cp.async: 128 rows x 256B
    {
        const __nv_bfloat16* Ep = g_E + (size_t)p * DIMK * DIMK;
        #pragma unroll
        for (int it = 0; it < 8; it++) {
            int id = it * 256 + tid;
            int row = id >> 4, c = id & 15;
            cpasync16(sb + S_B + row * TSTRIDE + c * 16, Ep + row * DIMK + c * 8);
        }
    }
    // first stage: raw fp32 z rows for tile t0
    {
        int base = off + t0 * 64;
        int rows = cnt - t0 * 64; if (rows > 64) rows = 64;
        #pragma unroll
        for (int it = 0; it < 8; it++) {
            int idx = it * 256 + tid;
            int r = idx >> 5, c4 = idx & 31;
            int rr = (r < rows) ? r : 0;
            int grow = __ldg(&g_perm[base + rr]);
            cpasync16(sb + S_STAGE + r * 512 + c4 * 16, Z + (size_t)grow * DIMK + c4 * 4);
        }
    }
    asm volatile("cp.async.commit_group;");

    for (int t = t0; t * 64 < cnt; t += TPP) {
        int base = off + t * 64;
        int rows = cnt - t * 64; if (rows > 64) rows = 64;

        asm volatile("cp.async.wait_group 0;" ::: "memory");
        __syncthreads();   // stage ready; prior-iter epilogue reads of A done

        if (tid < 64) sperm[tid] = g_perm[base + ((tid < rows) ? tid : 0)];

        // convert stage fp32 -> split bf16 A tiles
        #pragma unroll
        for (int it = 0; it < 8; it++) {
            int idx = it * 256 + tid;
            int r = idx >> 5, c4 = idx & 31;
            float4 v = *(const float4*)(smem + S_STAGE + r * 512 + c4 * 16);
            uint2 hi, lo; split4(v, hi, lo);
            *(uint2*)(smem + S_AHI + r * TSTRIDE + c4 * 8) = hi;
            *(uint2*)(smem + S_ALO + r * TSTRIDE + c4 * 8) = lo;
        }
        __syncthreads();   // stage consumed, A + sperm visible

        // prefetch next tile into stage (overlaps MMA + epilogue)
        int tn = t + TPP;
        if (tn * 64 < cnt) {
            int basen = off + tn * 64;
            int rowsn = cnt - tn * 64; if (rowsn > 64) rowsn = 64;
            #pragma unroll
            for (int it = 0; it < 8; it++) {
                int idx = it * 256 + tid;
                int r = idx >> 5, c4 = idx & 31;
                int rr = (r < rowsn) ? r : 0;
                int grow = __ldg(&g_perm[basen + rr]);
                cpasync16(sb + S_STAGE + r * 512 + c4 * 16, Z + (size_t)grow * DIMK + c4 * 4);
            }
            asm volatile("cp.async.commit_group;");
        }

        // ---- MMA: 2 chains x 8 k-steps ----
        float acc[2][4][4];
        #pragma unroll
        for (int mt = 0; mt < 2; mt++)
            #pragma unroll
            for (int nt = 0; nt < 4; nt++)
                #pragma unroll
                for (int i = 0; i < 4; i++) acc[mt][nt][i] = 0.f;

        #pragma unroll
        for (int ks = 0; ks < 8; ks++) {
            int kb = ks * 16;
            uint32_t ah[2][4], al[2][4];
            #pragma unroll
            for (int mt = 0; mt < 2; mt++) {
                uint32_t row = wm * 32 + mt * 16 + (lane & 15);
                uint32_t o = row * TSTRIDE + kb * 2 + ((lane >> 4) << 4);
                ldsm_x4(ah[mt], sb + S_AHI + o);
                ldsm_x4(al[mt], sb + S_ALO + o);
            }
            #pragma unroll
            for (int j = 0; j < 2; j++) {
                uint32_t n = wn * 32 + j * 16 + (lane & 15);
                uint32_t o = n * TSTRIDE + kb * 2 + ((lane >> 4) << 4);
                uint32_t qh[4];
                ldsm_x4(qh, sb + S_B + o);
                uint32_t b0[2] = {qh[0], qh[2]}, b1[2] = {qh[1], qh[3]};
                #pragma unroll
                for (int mt = 0; mt < 2; mt++) {
                    mma_bf16(acc[mt][j * 2 + 0], ah[mt], b0);
                    mma_bf16(acc[mt][j * 2 + 0], al[mt], b0);
                    mma_bf16(acc[mt][j * 2 + 1], ah[mt], b1);
                    mma_bf16(acc[mt][j * 2 + 1], al[mt], b1);
                }
            }
        }

        // ---- epilogue: out = acc + z (hi+lo from smem) + bias; scatter ----
        int gid = lane >> 2, tig = lane & 3;
        #pragma unroll
        for (int mt = 0; mt < 2; mt++) {
            int m0 = wm * 32 + mt * 16 + gid;
            #pragma unroll
            for (int half = 0; half < 2; half++) {
                int m = m0 + half * 8;
                if (m >= rows) continue;
                long gr = (long)sperm[m];
                #pragma unroll
                for (int nt = 0; nt < 4; nt++) {
                    int n = wn * 32 + nt * 8 + tig * 2;
                    __nv_bfloat162 zh = *(const __nv_bfloat162*)(smem + S_AHI + m * TSTRIDE + n * 2);
                    __nv_bfloat162 zl = *(const __nv_bfloat162*)(smem + S_ALO + m * TSTRIDE + n * 2);
                    float2 zhf = __bfloat1622float2(zh);
                    float2 zlf = __bfloat1622float2(zl);
                    float2 o;
                    o.x = acc[mt][nt][half * 2 + 0] + zhf.x + zlf.x + sbias[n];
                    o.y = acc[mt][nt][half * 2 + 1] + zhf.y + zlf.y + sbias[n + 1];
                    *(float2*)(Y + gr * DIMK + n) = o;
                }
            }
        }
    }
}

// ------------------------------ launch ------------------------------
extern "C" void kernel_launch(void* const* d_in, const int* in_sizes, int n_in,
                              void* d_out, int out_size) {
    const float* z    = (const float*)d_in[0];
    const int*   src  = (const int*)  d_in[1];
    const int*   tgt  = (const int*)  d_in[2];
    const float* enc  = (const float*)d_in[3];
    const float* dec  = (const float*)d_in[4];
    const float* cpar = (const float*)d_in[5];
    const float* dpar = (const float*)d_in[6];
    float* out = (float*)d_out;

    cudaFuncSetAttribute(k_precomp, cudaFuncAttributeMaxDynamicSharedMemorySize, PRE_SMEM);
    cudaFuncSetAttribute(k_main,    cudaFuncAttributeMaxDynamicSharedMemorySize, MAIN_SMEM);

    k_init<<<1, 256>>>();
    k_hist<<<256, 256>>>(src, tgt);
    k_scan<<<1, 256>>>();
    k_scatter<<<NB / 2048, 256>>>(src, tgt);
    k_precomp<<<NPAIR, 256, PRE_SMEM>>>(enc, dec, cpar, dpar);
    k_main<<<NPAIR * TPP, 256, MAIN_SMEM>>>(z, out);
}